// round 6
// baseline (speedup 1.0000x reference)
#include <cuda_runtime.h>
#include <cuda_bf16.h>
#include <math.h>
#include <stdint.h>

// ---------------------------------------------------------------------------
// Scratch (device globals; no dynamic allocation allowed)
// ---------------------------------------------------------------------------
__device__ float g_xn[4 * 1024 * 1024];     // normalized x     [B,C,T]
__device__ float g_qkv[4 * 3072 * 1024];    // qkv projections  [B,3C,T]
__device__ float g_attn[4 * 1024 * 1024];   // attention output [B,C,T]

// ---------------------------------------------------------------------------
// helpers
// ---------------------------------------------------------------------------
__device__ __forceinline__ uint32_t smem_u32(const void* p) {
    uint32_t a;
    asm("{ .reg .u64 t; cvta.to.shared.u64 t, %1; cvt.u32.u64 %0, t; }" : "=r"(a) : "l"(p));
    return a;
}
__device__ __forceinline__ uint32_t tf32u(float x) {
    uint32_t y; asm("cvt.rna.tf32.f32 %0, %1;" : "=r"(y) : "f"(x)); return y;
}
__device__ __forceinline__ float tf32f(float x) {
    return __uint_as_float(tf32u(x));
}
__device__ __forceinline__ void cp16(uint32_t dst, const void* src) {
    asm volatile("cp.async.cg.shared.global [%0], [%1], 16;" :: "r"(dst), "l"(src));
}
__device__ __forceinline__ void cp_commit() { asm volatile("cp.async.commit_group;"); }
__device__ __forceinline__ void cp_wait0() { asm volatile("cp.async.wait_group 0;" ::: "memory"); }
__device__ __forceinline__ void cp_wait1() { asm volatile("cp.async.wait_group 1;" ::: "memory"); }

// tf32 MMA; operands are raw fp32 bit patterns (HW truncates to tf32).
__device__ __forceinline__ void mma_tf32(float* c, const uint32_t* a, const uint32_t* b) {
    asm volatile(
        "mma.sync.aligned.m16n8k8.row.col.f32.tf32.tf32.f32 "
        "{%0,%1,%2,%3}, {%4,%5,%6,%7}, {%8,%9}, {%0,%1,%2,%3};"
        : "+f"(c[0]), "+f"(c[1]), "+f"(c[2]), "+f"(c[3])
        : "r"(a[0]), "r"(a[1]), "r"(a[2]), "r"(a[3]), "r"(b[0]), "r"(b[1]));
}

// ---------------------------------------------------------------------------
// TF32 tensor-core GEMM via mma.sync:
//   out[z,o,t] = sum_k W[o,k] * X[z,k,t] + bias[o] (+ R[z,o,t])
// CTA tile 128(o) x 128(t), 128 threads = 4 warps (2m x 2n), warp tile 64x64.
// K-tile 16, 3-stage cp.async ring, one __syncthreads per k-tile.
// ---------------------------------------------------------------------------
#define WPAD 20
#define XPAD 136
#define STAGE_F (128 * WPAD + 16 * XPAD)
#define GEMM_SMEM (3 * STAGE_F * 4)

__global__ __launch_bounds__(128, 2) void mma_gemm(const float* __restrict__ W,
                                                   const float* __restrict__ X,
                                                   const float* __restrict__ bias,
                                                   const float* __restrict__ R,
                                                   float* __restrict__ out, int O) {
    extern __shared__ float sm[];

    const int tid = threadIdx.x;
    const int wid = tid >> 5, lane = tid & 31;
    const int gid = lane >> 2, tg = lane & 3;
    const int warp_m = (wid & 1) * 64, warp_n = (wid >> 1) * 64;

    const int t0 = blockIdx.x * 128, o0 = blockIdx.y * 128, z = blockIdx.z;
    const float* Xb = X + (size_t)z * 1024 * 1024;

    float c[4][8][4];
#pragma unroll
    for (int mt = 0; mt < 4; mt++)
#pragma unroll
        for (int nt = 0; nt < 8; nt++)
#pragma unroll
            for (int e = 0; e < 4; e++) c[mt][nt][e] = 0.f;

    const uint32_t aS = smem_u32(sm);

    // fill one stage with k-tile kt (16 k-rows)
    auto issue = [&](int s, int kt) {
        const int k0 = kt * 16;
        uint32_t bW = aS + (uint32_t)(s * STAGE_F * 4);
        uint32_t bX = bW + (uint32_t)(128 * WPAD * 4);
#pragma unroll
        for (int i = 0; i < 4; i++) {
            int id = tid * 4 + i;                  // 0..511
            int row = id >> 2, kv = id & 3;        // W: 128 rows x 4 float4
            cp16(bW + (uint32_t)((row * WPAD + kv * 4) * 4),
                 W + (size_t)(o0 + row) * 1024 + k0 + kv * 4);
        }
#pragma unroll
        for (int i = 0; i < 4; i++) {
            int id = tid * 4 + i;
            int krow = id >> 5, tv = id & 31;      // X: 16 rows x 32 float4
            cp16(bX + (uint32_t)((krow * XPAD + tv * 4) * 4),
                 Xb + (size_t)(k0 + krow) * 1024 + t0 + tv * 4);
        }
        cp_commit();
    };

    issue(0, 0);
    issue(1, 1);

    int stage = 0;
    for (int kt = 0; kt < 64; kt++) {
        cp_wait1();          // k-tile kt's group complete (kt+1 may be in flight)
        __syncthreads();     // all threads' copies visible; prior compute done
        if (kt + 2 < 64) issue(stage == 0 ? 2 : stage - 1, kt + 2);

        const uint32_t* wb = (const uint32_t*)(sm + stage * STAGE_F);
        const uint32_t* xb = wb + 128 * WPAD;

#pragma unroll
        for (int ks = 0; ks < 2; ks++) {
            const int kk = ks * 8;
            uint32_t af[4][4];
#pragma unroll
            for (int mt = 0; mt < 4; mt++) {
                const uint32_t* wr = wb + (warp_m + mt * 16 + gid) * WPAD + kk + tg;
                af[mt][0] = wr[0];
                af[mt][1] = wr[8 * WPAD];
                af[mt][2] = wr[4];
                af[mt][3] = wr[8 * WPAD + 4];
            }
            uint32_t bf[8][2];
#pragma unroll
            for (int nt = 0; nt < 8; nt++) {
                const uint32_t* xr = xb + (kk + tg) * XPAD + warp_n + nt * 8 + gid;
                bf[nt][0] = xr[0];
                bf[nt][1] = xr[4 * XPAD];
            }
#pragma unroll
            for (int mt = 0; mt < 4; mt++)
#pragma unroll
                for (int nt = 0; nt < 8; nt++)
                    mma_tf32(c[mt][nt], af[mt], bf[nt]);
        }
        stage = (stage == 2) ? 0 : stage + 1;
    }

    // epilogue
#pragma unroll
    for (int mt = 0; mt < 4; mt++) {
#pragma unroll
        for (int half = 0; half < 2; half++) {
            int o = o0 + warp_m + mt * 16 + gid + half * 8;
            float bv = bias[o];
            size_t rowbase = ((size_t)z * O + o) * 1024;
#pragma unroll
            for (int nt = 0; nt < 8; nt++) {
                int t = t0 + warp_n + nt * 8 + tg * 2;
                float2 v;
                v.x = c[mt][nt][half * 2 + 0] + bv;
                v.y = c[mt][nt][half * 2 + 1] + bv;
                if (R) {
                    float2 rr = *(const float2*)(R + rowbase + t);
                    v.x += rr.x; v.y += rr.y;
                }
                *(float2*)(out + rowbase + t) = v;
            }
        }
    }
}

// ---------------------------------------------------------------------------
// GroupNorm: one block per (batch, group); 1024 threads, float4 path.
// ---------------------------------------------------------------------------
__global__ __launch_bounds__(1024) void gn_kernel(const float* __restrict__ x,
                                                  const float* __restrict__ w,
                                                  const float* __restrict__ b,
                                                  float* __restrict__ xn) {
    int batch = blockIdx.x >> 5;
    int g = blockIdx.x & 31;
    const float4* xp = (const float4*)(x + ((size_t)batch * 1024 + g * 32) * 1024);
    float4* xo = (float4*)(xn + ((size_t)batch * 1024 + g * 32) * 1024);

    float s = 0.f, ss = 0.f;
#pragma unroll
    for (int r = 0; r < 8; r++) {
        float4 v = xp[r * 1024 + threadIdx.x];
        s += v.x + v.y + v.z + v.w;
        ss += v.x * v.x + v.y * v.y + v.z * v.z + v.w * v.w;
    }
#pragma unroll
    for (int o = 16; o; o >>= 1) {
        s  += __shfl_xor_sync(0xffffffffu, s, o);
        ss += __shfl_xor_sync(0xffffffffu, ss, o);
    }
    __shared__ float red[66];
    int warp = threadIdx.x >> 5, lane = threadIdx.x & 31;
    if (lane == 0) { red[warp] = s; red[warp + 32] = ss; }
    __syncthreads();
    if (threadIdx.x == 0) {
        float ts = 0.f, tss = 0.f;
#pragma unroll
        for (int i = 0; i < 32; i++) { ts += red[i]; tss += red[i + 32]; }
        float mu = ts * (1.f / 32768.f);
        float var = tss * (1.f / 32768.f) - mu * mu;
        red[64] = mu;
        red[65] = rsqrtf(var + 1e-5f);
    }
    __syncthreads();
    float mu = red[64], inv = red[65];
#pragma unroll
    for (int r = 0; r < 8; r++) {
        int idx4 = r * 1024 + threadIdx.x;
        int c = g * 32 + (idx4 >> 8);
        float sc = inv * w[c];
        float sh = b[c] - mu * sc;
        float4 v = xp[idx4];
        v.x = v.x * sc + sh; v.y = v.y * sc + sh;
        v.z = v.z * sc + sh; v.w = v.w * sc + sh;
        xo[idx4] = v;
    }
}

// ---------------------------------------------------------------------------
// Flash attention with tf32 mma.sync.
// Block = one (b,h) x 64-query tile. 256 threads, 8 warps (4 m x 2 n).
// ---------------------------------------------------------------------------
#define APITCH 72
#define KPITCH 68
#define ATTN_SMEM ((64 * APITCH * 3 + 64 * KPITCH + 256 + 256 + 192) * 4)

__global__ __launch_bounds__(256) void attn_mma(const float* __restrict__ qkv,
                                                float* __restrict__ out) {
    extern __shared__ float sm[];
    float* Qs   = sm;                    // [64][APITCH]
    float* Kt   = Qs + 64 * APITCH;      // [64][KPITCH]  j-major
    float* Vs   = Kt + 64 * KPITCH;      // [64][APITCH]
    float* Ss   = Vs + 64 * APITCH;      // [64][APITCH]  probs (tf32-rounded)
    float* pm   = Ss + 64 * APITCH;      // [4][64] partial max
    float* ps   = pm + 256;              // [4][64] partial sum
    float* marr = ps + 256;              // [64] running max
    float* lar  = marr + 64;             // [64] running sum
    float* aar  = lar + 64;              // [64] alpha

    const int bh = blockIdx.y;
    const int b = bh >> 4, h = bh & 15;
    const int t0 = blockIdx.x * 64;
    const float* qp = qkv + ((size_t)b * 3072 + h * 192) * 1024;
    const float* kp = qp + 64 * 1024;
    const float* vp = qp + 128 * 1024;

    const int tid = threadIdx.x, wid = tid >> 5, lane = tid & 31;
    const int gid = lane >> 2, tg = lane & 3;
    const int wq = wid & 3;
    const int warp_m = wq * 16;
    const int warp_n = (wid >> 2) * 32;

    // Q tile [c][i] (raw fp32; MMA truncates)
#pragma unroll
    for (int r = 0; r < 4; r++) {
        int id = r * 256 + tid;
        int cc = id >> 4, i4 = (id & 15) * 4;
        *(float4*)&Qs[cc * APITCH + i4] = *(const float4*)(qp + (size_t)cc * 1024 + t0 + i4);
    }
    if (tid < 64) { marr[tid] = -1e30f; lar[tid] = 0.f; }

    float o[4][4];
#pragma unroll
    for (int nt = 0; nt < 4; nt++)
#pragma unroll
        for (int e = 0; e < 4; e++) o[nt][e] = 0.f;

    for (int s0 = 0; s0 < 1024; s0 += 64) {
        __syncthreads();

        // K tile transposed: Kt[j][c]
#pragma unroll
        for (int r = 0; r < 16; r++) {
            int id = r * 256 + tid;
            int cc = id >> 6, j = id & 63;
            Kt[j * KPITCH + cc] = kp[(size_t)cc * 1024 + s0 + j];
        }
        // V tile natural: Vs[c][j]
#pragma unroll
        for (int r = 0; r < 4; r++) {
            int id = r * 256 + tid;
            int cc = id >> 4, j4 = (id & 15) * 4;
            *(float4*)&Vs[cc * APITCH + j4] = *(const float4*)(vp + (size_t)cc * 1024 + s0 + j4);
        }
        __syncthreads();

        // ---- S = Kt * Q ----
        float sc[4][4];
#pragma unroll
        for (int nt = 0; nt < 4; nt++)
#pragma unroll
            for (int e = 0; e < 4; e++) sc[nt][e] = 0.f;

#pragma unroll
        for (int ks = 0; ks < 8; ks++) {
            int kk = ks * 8;
            uint32_t a[4];
            a[0] = __float_as_uint(Kt[(warp_m + gid) * KPITCH + kk + tg]);
            a[1] = __float_as_uint(Kt[(warp_m + gid + 8) * KPITCH + kk + tg]);
            a[2] = __float_as_uint(Kt[(warp_m + gid) * KPITCH + kk + tg + 4]);
            a[3] = __float_as_uint(Kt[(warp_m + gid + 8) * KPITCH + kk + tg + 4]);
#pragma unroll
            for (int nt = 0; nt < 4; nt++) {
                uint32_t bb[2];
                bb[0] = __float_as_uint(Qs[(kk + tg) * APITCH + warp_n + nt * 8 + gid]);
                bb[1] = __float_as_uint(Qs[(kk + tg + 4) * APITCH + warp_n + nt * 8 + gid]);
                mma_tf32(sc[nt], a, bb);
            }
        }
#pragma unroll
        for (int nt = 0; nt < 4; nt++)
#pragma unroll
            for (int e = 0; e < 4; e++) sc[nt][e] *= 0.125f;

        // per-warp column max -> pm[wq][i]
#pragma unroll
        for (int nt = 0; nt < 4; nt++) {
            float m0 = fmaxf(sc[nt][0], sc[nt][2]);
            float m1 = fmaxf(sc[nt][1], sc[nt][3]);
#pragma unroll
            for (int mk = 4; mk <= 16; mk <<= 1) {
                m0 = fmaxf(m0, __shfl_xor_sync(0xffffffffu, m0, mk));
                m1 = fmaxf(m1, __shfl_xor_sync(0xffffffffu, m1, mk));
            }
            if (gid == 0) {
                int n = warp_n + nt * 8 + tg * 2;
                pm[wq * 64 + n] = m0;
                pm[wq * 64 + n + 1] = m1;
            }
        }
        __syncthreads();

        // phase A: exp + store probs + partial sums
#pragma unroll
        for (int nt = 0; nt < 4; nt++) {
            int n = warp_n + nt * 8 + tg * 2;
#pragma unroll
            for (int e = 0; e < 2; e++) {
                int i = n + e;
                float mn = fmaxf(fmaxf(fmaxf(pm[i], pm[64 + i]),
                                       fmaxf(pm[128 + i], pm[192 + i])), marr[i]);
                float p0 = tf32f(__expf(sc[nt][e] - mn));
                float p1 = tf32f(__expf(sc[nt][e + 2] - mn));
                Ss[(warp_m + gid) * APITCH + i] = p0;
                Ss[(warp_m + gid + 8) * APITCH + i] = p1;
                float su = p0 + p1;
#pragma unroll
                for (int mk = 4; mk <= 16; mk <<= 1)
                    su += __shfl_xor_sync(0xffffffffu, su, mk);
                if (gid == 0) ps[wq * 64 + i] = su;
            }
        }
        __syncthreads();

        // phase B: designated writers update running stats
        if (wq == 0 && gid == 0) {
#pragma unroll
            for (int nt = 0; nt < 4; nt++) {
#pragma unroll
                for (int e = 0; e < 2; e++) {
                    int i = warp_n + nt * 8 + tg * 2 + e;
                    float mo = marr[i];
                    float mn = fmaxf(fmaxf(fmaxf(pm[i], pm[64 + i]),
                                           fmaxf(pm[128 + i], pm[192 + i])), mo);
                    float al = __expf(mo - mn);
                    float st = ps[i] + ps[64 + i] + ps[128 + i] + ps[192 + i];
                    lar[i] = lar[i] * al + st;
                    marr[i] = mn;
                    aar[i] = al;
                }
            }
        }
        __syncthreads();

        // ---- O = V * P ----
#pragma unroll
        for (int nt = 0; nt < 4; nt++) {
            int n = warp_n + nt * 8 + tg * 2;
            float a0 = aar[n], a1 = aar[n + 1];
            o[nt][0] *= a0; o[nt][1] *= a1; o[nt][2] *= a0; o[nt][3] *= a1;
        }
#pragma unroll
        for (int ks = 0; ks < 8; ks++) {
            int kk = ks * 8;
            uint32_t a[4];
            a[0] = __float_as_uint(Vs[(warp_m + gid) * APITCH + kk + tg]);
            a[1] = __float_as_uint(Vs[(warp_m + gid + 8) * APITCH + kk + tg]);
            a[2] = __float_as_uint(Vs[(warp_m + gid) * APITCH + kk + tg + 4]);
            a[3] = __float_as_uint(Vs[(warp_m + gid + 8) * APITCH + kk + tg + 4]);
#pragma unroll
            for (int nt = 0; nt < 4; nt++) {
                uint32_t bb[2];
                bb[0] = __float_as_uint(Ss[(kk + tg) * APITCH + warp_n + nt * 8 + gid]);
                bb[1] = __float_as_uint(Ss[(kk + tg + 4) * APITCH + warp_n + nt * 8 + gid]);
                mma_tf32(o[nt], a, bb);
            }
        }
    }
    __syncthreads();

    // normalize + write Ot[c][i] to attn[b, h*64+c, t0+i]
#pragma unroll
    for (int nt = 0; nt < 4; nt++) {
        int n = warp_n + nt * 8 + tg * 2;
        float li0 = 1.f / lar[n], li1 = 1.f / lar[n + 1];
        size_t base0 = ((size_t)b * 1024 + h * 64 + warp_m + gid) * 1024 + t0 + n;
        float2 v0 = { o[nt][0] * li0, o[nt][1] * li1 };
        *(float2*)(out + base0) = v0;
        float2 v1 = { o[nt][2] * li0, o[nt][3] * li1 };
        *(float2*)(out + base0 + 8 * 1024) = v1;
    }
}

// ---------------------------------------------------------------------------
extern "C" void kernel_launch(void* const* d_in, const int* in_sizes, int n_in,
                              void* d_out, int out_size) {
    const float* x      = (const float*)d_in[0];
    const float* nw     = (const float*)d_in[1];
    const float* nb     = (const float*)d_in[2];
    const float* qkv_w  = (const float*)d_in[3];
    const float* qkv_b  = (const float*)d_in[4];
    const float* proj_w = (const float*)d_in[5];
    const float* proj_b = (const float*)d_in[6];
    float* out = (float*)d_out;

    float *xn, *qkv, *attn;
    cudaGetSymbolAddress((void**)&xn,   g_xn);
    cudaGetSymbolAddress((void**)&qkv,  g_qkv);
    cudaGetSymbolAddress((void**)&attn, g_attn);

    // 1. GroupNorm
    gn_kernel<<<128, 1024>>>(x, nw, nb, xn);

    // 2. QKV projection (tf32 mma.sync)
    cudaFuncSetAttribute(mma_gemm, cudaFuncAttributeMaxDynamicSharedMemorySize, GEMM_SMEM);
    mma_gemm<<<dim3(8, 24, 4), 128, GEMM_SMEM>>>(qkv_w, xn, qkv_b, nullptr, qkv, 3072);

    // 3. Attention (tf32 mma.sync flash)
    cudaFuncSetAttribute(attn_mma, cudaFuncAttributeMaxDynamicSharedMemorySize, ATTN_SMEM);
    attn_mma<<<dim3(16, 64), 256, ATTN_SMEM>>>(qkv, attn);

    // 4. Output projection + bias + residual (tf32 mma.sync)
    mma_gemm<<<dim3(8, 8, 4), 128, GEMM_SMEM>>>(proj_w, attn, proj_b, x, out, 1024);
}

// round 7
// speedup vs baseline: 1.1260x; 1.1260x over previous
#include <cuda_runtime.h>
#include <cuda_bf16.h>
#include <math.h>
#include <stdint.h>

// ---------------------------------------------------------------------------
// Scratch (device globals; no dynamic allocation allowed)
// ---------------------------------------------------------------------------
__device__ float g_xn[4 * 1024 * 1024];     // normalized x     [B,C,T]
__device__ float g_qkv[4 * 3072 * 1024];    // qkv projections  [B,3C,T]
__device__ float g_attn[4 * 1024 * 1024];   // attention output [B,C,T]

// ---------------------------------------------------------------------------
// helpers
// ---------------------------------------------------------------------------
__device__ __forceinline__ uint32_t smem_u32(const void* p) {
    uint32_t a;
    asm("{ .reg .u64 t; cvta.to.shared.u64 t, %1; cvt.u32.u64 %0, t; }" : "=r"(a) : "l"(p));
    return a;
}
__device__ __forceinline__ uint32_t tf32u(float x) {
    uint32_t y; asm("cvt.rna.tf32.f32 %0, %1;" : "=r"(y) : "f"(x)); return y;
}
__device__ __forceinline__ float tf32f(float x) {
    return __uint_as_float(tf32u(x));
}
__device__ __forceinline__ void cp16(uint32_t dst, const void* src) {
    asm volatile("cp.async.cg.shared.global [%0], [%1], 16;" :: "r"(dst), "l"(src));
}
__device__ __forceinline__ void cp_commit() { asm volatile("cp.async.commit_group;"); }
__device__ __forceinline__ void cp_wait0() { asm volatile("cp.async.wait_group 0;" ::: "memory"); }
__device__ __forceinline__ void cp_wait1() { asm volatile("cp.async.wait_group 1;" ::: "memory"); }

// tf32 MMA; operands are raw fp32 bit patterns (HW truncates to tf32).
__device__ __forceinline__ void mma_tf32(float* c, const uint32_t* a, const uint32_t* b) {
    asm volatile(
        "mma.sync.aligned.m16n8k8.row.col.f32.tf32.tf32.f32 "
        "{%0,%1,%2,%3}, {%4,%5,%6,%7}, {%8,%9}, {%0,%1,%2,%3};"
        : "+f"(c[0]), "+f"(c[1]), "+f"(c[2]), "+f"(c[3])
        : "r"(a[0]), "r"(a[1]), "r"(a[2]), "r"(a[3]), "r"(b[0]), "r"(b[1]));
}

// ---------------------------------------------------------------------------
// TF32 tensor-core GEMM via mma.sync (R5 configuration — best measured):
//   out[z,o,t] = sum_k W[o,k] * X[z,k,t] + bias[o] (+ R[z,o,t])
// CTA tile 128(o) x 128(t), 256 threads (8 warps 4m x 2n), K-tile 32,
// double-buffered cp.async.
// ---------------------------------------------------------------------------
#define WPAD 36
#define XPAD 136
#define GEMM_SMEM ((2 * 128 * WPAD + 2 * 32 * XPAD) * 4)

__global__ __launch_bounds__(256, 2) void mma_gemm(const float* __restrict__ W,
                                                   const float* __restrict__ X,
                                                   const float* __restrict__ bias,
                                                   const float* __restrict__ R,
                                                   float* __restrict__ out, int O) {
    extern __shared__ float sm[];
    float* sW = sm;                       // [2][128][WPAD]
    float* sX = sm + 2 * 128 * WPAD;      // [2][32][XPAD]

    const int tid = threadIdx.x;
    const int wid = tid >> 5, lane = tid & 31;
    const int gid = lane >> 2, tg = lane & 3;
    const int warp_m = (wid & 3) * 32, warp_n = (wid >> 2) * 64;

    const int t0 = blockIdx.x * 128, o0 = blockIdx.y * 128, z = blockIdx.z;
    const float* Xb = X + (size_t)z * 1024 * 1024;

    float c[2][8][4];
#pragma unroll
    for (int mt = 0; mt < 2; mt++)
#pragma unroll
        for (int nt = 0; nt < 8; nt++)
#pragma unroll
            for (int e = 0; e < 4; e++) c[mt][nt][e] = 0.f;

    uint32_t aW = smem_u32(sW), aX = smem_u32(sX);

    auto issue = [&](int buf, int kt) {
        const int k0 = kt * 32;
        uint32_t bW = aW + (uint32_t)(buf * 128 * WPAD * 4);
        uint32_t bX = aX + (uint32_t)(buf * 32 * XPAD * 4);
#pragma unroll
        for (int i = 0; i < 4; i++) {
            int id = tid * 4 + i;
            int row = id >> 3, kv = id & 7;
            cp16(bW + (uint32_t)((row * WPAD + kv * 4) * 4),
                 W + (size_t)(o0 + row) * 1024 + k0 + kv * 4);
        }
#pragma unroll
        for (int i = 0; i < 4; i++) {
            int id = tid * 4 + i;
            int krow = id >> 5, tv = id & 31;
            cp16(bX + (uint32_t)((krow * XPAD + tv * 4) * 4),
                 Xb + (size_t)(k0 + krow) * 1024 + t0 + tv * 4);
        }
        cp_commit();
    };

    issue(0, 0);

    for (int kt = 0; kt < 32; kt++) {
        const int buf = kt & 1;
        if (kt + 1 < 32) {
            issue(buf ^ 1, kt + 1);
            cp_wait1();
        } else {
            cp_wait0();
        }
        __syncthreads();

        const uint32_t* wb = (const uint32_t*)(sW + buf * 128 * WPAD);
        const uint32_t* xb = (const uint32_t*)(sX + buf * 32 * XPAD);

#pragma unroll
        for (int ks = 0; ks < 4; ks++) {
            const int kk = ks * 8;
            uint32_t af[2][4];
#pragma unroll
            for (int mt = 0; mt < 2; mt++) {
                const uint32_t* wr = wb + (warp_m + mt * 16 + gid) * WPAD + kk + tg;
                af[mt][0] = wr[0];
                af[mt][1] = wr[8 * WPAD];
                af[mt][2] = wr[4];
                af[mt][3] = wr[8 * WPAD + 4];
            }
            uint32_t bf[8][2];
#pragma unroll
            for (int nt = 0; nt < 8; nt++) {
                const uint32_t* xr = xb + (kk + tg) * XPAD + warp_n + nt * 8 + gid;
                bf[nt][0] = xr[0];
                bf[nt][1] = xr[4 * XPAD];
            }
#pragma unroll
            for (int mt = 0; mt < 2; mt++)
#pragma unroll
                for (int nt = 0; nt < 8; nt++)
                    mma_tf32(c[mt][nt], af[mt], bf[nt]);
        }
        __syncthreads();
    }

#pragma unroll
    for (int mt = 0; mt < 2; mt++) {
#pragma unroll
        for (int half = 0; half < 2; half++) {
            int o = o0 + warp_m + mt * 16 + gid + half * 8;
            float bv = bias[o];
            size_t rowbase = ((size_t)z * O + o) * 1024;
#pragma unroll
            for (int nt = 0; nt < 8; nt++) {
                int t = t0 + warp_n + nt * 8 + tg * 2;
                float2 v;
                v.x = c[mt][nt][half * 2 + 0] + bv;
                v.y = c[mt][nt][half * 2 + 1] + bv;
                if (R) {
                    float2 rr = *(const float2*)(R + rowbase + t);
                    v.x += rr.x; v.y += rr.y;
                }
                *(float2*)(out + rowbase + t) = v;
            }
        }
    }
}

// ---------------------------------------------------------------------------
// GroupNorm: one block per (batch, group); 1024 threads, float4 path.
// ---------------------------------------------------------------------------
__global__ __launch_bounds__(1024) void gn_kernel(const float* __restrict__ x,
                                                  const float* __restrict__ w,
                                                  const float* __restrict__ b,
                                                  float* __restrict__ xn) {
    int batch = blockIdx.x >> 5;
    int g = blockIdx.x & 31;
    const float4* xp = (const float4*)(x + ((size_t)batch * 1024 + g * 32) * 1024);
    float4* xo = (float4*)(xn + ((size_t)batch * 1024 + g * 32) * 1024);

    float s = 0.f, ss = 0.f;
#pragma unroll
    for (int r = 0; r < 8; r++) {
        float4 v = xp[r * 1024 + threadIdx.x];
        s += v.x + v.y + v.z + v.w;
        ss += v.x * v.x + v.y * v.y + v.z * v.z + v.w * v.w;
    }
#pragma unroll
    for (int o = 16; o; o >>= 1) {
        s  += __shfl_xor_sync(0xffffffffu, s, o);
        ss += __shfl_xor_sync(0xffffffffu, ss, o);
    }
    __shared__ float red[66];
    int warp = threadIdx.x >> 5, lane = threadIdx.x & 31;
    if (lane == 0) { red[warp] = s; red[warp + 32] = ss; }
    __syncthreads();
    if (threadIdx.x == 0) {
        float ts = 0.f, tss = 0.f;
#pragma unroll
        for (int i = 0; i < 32; i++) { ts += red[i]; tss += red[i + 32]; }
        float mu = ts * (1.f / 32768.f);
        float var = tss * (1.f / 32768.f) - mu * mu;
        red[64] = mu;
        red[65] = rsqrtf(var + 1e-5f);
    }
    __syncthreads();
    float mu = red[64], inv = red[65];
#pragma unroll
    for (int r = 0; r < 8; r++) {
        int idx4 = r * 1024 + threadIdx.x;
        int c = g * 32 + (idx4 >> 8);
        float sc = inv * w[c];
        float sh = b[c] - mu * sc;
        float4 v = xp[idx4];
        v.x = v.x * sc + sh; v.y = v.y * sc + sh;
        v.z = v.z * sc + sh; v.w = v.w * sc + sh;
        xo[idx4] = v;
    }
}

// ---------------------------------------------------------------------------
// Flash attention, warp-owns-columns decomposition.
// Block = one (b,h) x 64-query tile; 256 threads = 8 warps.
// Each warp owns 8 query columns i = wid*8..wid*8+7 for the whole kernel:
//   S phase:  S[all 64 j][own 8 i] = Kt x Q   (A=Kt broadcast, B=Q own cols)
//   softmax:  warp-local (register m/l, shfl over gid bits only)
//   PV phase: O[all 64 c][own 8 i] += V x P   (A=Vs broadcast, B=own Ss cols)
// 2 __syncthreads per s-tile (K/V smem hazard only) + 1 __syncwarp.
// ---------------------------------------------------------------------------
#define BP 72   // Qs / Ss pitch (B operands): bank = 8*tg + gid, conflict-free
#define AP 68   // Kt / Vs pitch (A operands): bank = 4*gid + tg, conflict-free
#define ATTN_SMEM ((64 * BP * 2 + 64 * AP * 2) * 4)

__global__ __launch_bounds__(256, 2) void attn_mma(const float* __restrict__ qkv,
                                                   float* __restrict__ out) {
    extern __shared__ float sm[];
    float* Qs = sm;                 // [64 c][BP]
    float* Ss = Qs + 64 * BP;       // [64 j][BP] probs, warp-private columns
    float* Kt = Ss + 64 * BP;       // [64 j][AP]
    float* Vs = Kt + 64 * AP;       // [64 c][AP]

    const int bh = blockIdx.y;
    const int b = bh >> 4, h = bh & 15;
    const int t0 = blockIdx.x * 64;
    const float* qp = qkv + ((size_t)b * 3072 + h * 192) * 1024;
    const float* kp = qp + 64 * 1024;
    const float* vp = qp + 128 * 1024;

    const int tid = threadIdx.x, wid = tid >> 5, lane = tid & 31;
    const int gid = lane >> 2, tg = lane & 3;
    const int i0 = wid * 8;                 // this warp's query-column base

    // Q tile [c][i]
#pragma unroll
    for (int r = 0; r < 4; r++) {
        int id = r * 256 + tid;
        int cc = id >> 4, i4 = (id & 15) * 4;
        *(float4*)&Qs[cc * BP + i4] = *(const float4*)(qp + (size_t)cc * 1024 + t0 + i4);
    }

    float o[4][4];
#pragma unroll
    for (int mt = 0; mt < 4; mt++)
#pragma unroll
        for (int e = 0; e < 4; e++) o[mt][e] = 0.f;
    float m_run[2] = { -1e30f, -1e30f };
    float l_run[2] = { 0.f, 0.f };

    for (int s0 = 0; s0 < 1024; s0 += 64) {
        __syncthreads();   // prior tile's PV reads done before overwrite

        // K transposed: Kt[j][c]
#pragma unroll
        for (int r = 0; r < 16; r++) {
            int id = r * 256 + tid;
            int cc = id >> 6, j = id & 63;
            Kt[j * AP + cc] = kp[(size_t)cc * 1024 + s0 + j];
        }
        // V natural: Vs[c][j]
#pragma unroll
        for (int r = 0; r < 4; r++) {
            int id = r * 256 + tid;
            int cc = id >> 4, j4 = (id & 15) * 4;
            *(float4*)&Vs[cc * AP + j4] = *(const float4*)(vp + (size_t)cc * 1024 + s0 + j4);
        }
        __syncthreads();

        // ---- S = Kt * Q (warp computes all 64 j for its 8 columns) ----
        float sc[4][4];
#pragma unroll
        for (int mt = 0; mt < 4; mt++)
#pragma unroll
            for (int e = 0; e < 4; e++) sc[mt][e] = 0.f;

#pragma unroll
        for (int ks = 0; ks < 8; ks++) {
            int kk = ks * 8;
            uint32_t bb[2];
            bb[0] = __float_as_uint(Qs[(kk + tg) * BP + i0 + gid]);
            bb[1] = __float_as_uint(Qs[(kk + tg + 4) * BP + i0 + gid]);
#pragma unroll
            for (int mt = 0; mt < 4; mt++) {
                uint32_t a[4];
                a[0] = __float_as_uint(Kt[(mt * 16 + gid) * AP + kk + tg]);
                a[1] = __float_as_uint(Kt[(mt * 16 + gid + 8) * AP + kk + tg]);
                a[2] = __float_as_uint(Kt[(mt * 16 + gid) * AP + kk + tg + 4]);
                a[3] = __float_as_uint(Kt[(mt * 16 + gid + 8) * AP + kk + tg + 4]);
                mma_tf32(sc[mt], a, bb);
            }
        }

        // ---- warp-local online softmax (columns i0+2tg, i0+2tg+1) ----
        float alpha[2], psum[2];
#pragma unroll
        for (int e = 0; e < 2; e++) {
            float cm = fmaxf(fmaxf(sc[0][e], sc[0][e + 2]), fmaxf(sc[1][e], sc[1][e + 2]));
            cm = fmaxf(cm, fmaxf(fmaxf(sc[2][e], sc[2][e + 2]), fmaxf(sc[3][e], sc[3][e + 2])));
            cm *= 0.125f;
#pragma unroll
            for (int mk = 4; mk <= 16; mk <<= 1)
                cm = fmaxf(cm, __shfl_xor_sync(0xffffffffu, cm, mk));
            float mn = fmaxf(m_run[e], cm);
            alpha[e] = __expf(m_run[e] - mn);
            m_run[e] = mn;
            psum[e] = 0.f;
        }
#pragma unroll
        for (int mt = 0; mt < 4; mt++) {
#pragma unroll
            for (int e = 0; e < 2; e++) {
                float p0 = tf32f(__expf(sc[mt][e] * 0.125f - m_run[e]));
                float p1 = tf32f(__expf(sc[mt][e + 2] * 0.125f - m_run[e]));
                Ss[(mt * 16 + gid) * BP + i0 + tg * 2 + e] = p0;
                Ss[(mt * 16 + gid + 8) * BP + i0 + tg * 2 + e] = p1;
                psum[e] += p0 + p1;
            }
        }
#pragma unroll
        for (int e = 0; e < 2; e++) {
#pragma unroll
            for (int mk = 4; mk <= 16; mk <<= 1)
                psum[e] += __shfl_xor_sync(0xffffffffu, psum[e], mk);
            l_run[e] = l_run[e] * alpha[e] + psum[e];
        }

        // rescale O
#pragma unroll
        for (int mt = 0; mt < 4; mt++) {
            o[mt][0] *= alpha[0]; o[mt][2] *= alpha[0];
            o[mt][1] *= alpha[1]; o[mt][3] *= alpha[1];
        }
        __syncwarp();   // P columns visible within warp

        // ---- O += V * P ----
#pragma unroll
        for (int ks = 0; ks < 8; ks++) {
            int kk = ks * 8;
            uint32_t bb[2];
            bb[0] = __float_as_uint(Ss[(kk + tg) * BP + i0 + gid]);
            bb[1] = __float_as_uint(Ss[(kk + tg + 4) * BP + i0 + gid]);
#pragma unroll
            for (int mt = 0; mt < 4; mt++) {
                uint32_t a[4];
                a[0] = __float_as_uint(Vs[(mt * 16 + gid) * AP + kk + tg]);
                a[1] = __float_as_uint(Vs[(mt * 16 + gid + 8) * AP + kk + tg]);
                a[2] = __float_as_uint(Vs[(mt * 16 + gid) * AP + kk + tg + 4]);
                a[3] = __float_as_uint(Vs[(mt * 16 + gid + 8) * AP + kk + tg + 4]);
                mma_tf32(o[mt], a, bb);
            }
        }
    }

    // normalize + write: rows c = mt*16+gid(+8), cols i0+2tg(+1)
    float li0 = 1.f / l_run[0], li1 = 1.f / l_run[1];
#pragma unroll
    for (int mt = 0; mt < 4; mt++) {
        size_t base = ((size_t)b * 1024 + h * 64 + mt * 16 + gid) * 1024 + t0 + i0 + tg * 2;
        float2 v0 = { o[mt][0] * li0, o[mt][1] * li1 };
        *(float2*)(out + base) = v0;
        float2 v1 = { o[mt][2] * li0, o[mt][3] * li1 };
        *(float2*)(out + base + 8 * 1024) = v1;
    }
}

// ---------------------------------------------------------------------------
extern "C" void kernel_launch(void* const* d_in, const int* in_sizes, int n_in,
                              void* d_out, int out_size) {
    const float* x      = (const float*)d_in[0];
    const float* nw     = (const float*)d_in[1];
    const float* nb     = (const float*)d_in[2];
    const float* qkv_w  = (const float*)d_in[3];
    const float* qkv_b  = (const float*)d_in[4];
    const float* proj_w = (const float*)d_in[5];
    const float* proj_b = (const float*)d_in[6];
    float* out = (float*)d_out;

    float *xn, *qkv, *attn;
    cudaGetSymbolAddress((void**)&xn,   g_xn);
    cudaGetSymbolAddress((void**)&qkv,  g_qkv);
    cudaGetSymbolAddress((void**)&attn, g_attn);

    // 1. GroupNorm
    gn_kernel<<<128, 1024>>>(x, nw, nb, xn);

    // 2. QKV projection (tf32 mma.sync)
    cudaFuncSetAttribute(mma_gemm, cudaFuncAttributeMaxDynamicSharedMemorySize, GEMM_SMEM);
    mma_gemm<<<dim3(8, 24, 4), 256, GEMM_SMEM>>>(qkv_w, xn, qkv_b, nullptr, qkv, 3072);

    // 3. Attention (tf32 mma.sync flash, warp-owns-columns)
    cudaFuncSetAttribute(attn_mma, cudaFuncAttributeMaxDynamicSharedMemorySize, ATTN_SMEM);
    attn_mma<<<dim3(16, 64), 256, ATTN_SMEM>>>(qkv, attn);

    // 4. Output projection + bias + residual (tf32 mma.sync)
    mma_gemm<<<dim3(8, 8, 4), 256, GEMM_SMEM>>>(proj_w, attn, proj_b, x, out, 1024);
}

// round 8
// speedup vs baseline: 2.0193x; 1.7933x over previous
#include <cuda_runtime.h>
#include <cuda_bf16.h>
#include <math.h>
#include <stdint.h>

// ---------------------------------------------------------------------------
// Scratch (device globals; no dynamic allocation allowed)
// ---------------------------------------------------------------------------
__device__ uint16_t g_wq[3072 * 1024];        // qkv_w  bf16 [o][k]
__device__ uint16_t g_wp[1024 * 1024];        // proj_w bf16 [o][k]
__device__ uint32_t g_xnp[4 * 512 * 1024];    // xn  packed bf16 pairs [b][c/2][t]
__device__ uint16_t g_qkvb[4 * 3072 * 1024];  // qkv bf16 [b][3C][t]
__device__ uint32_t g_attnp[4 * 512 * 1024];  // attn packed bf16 pairs [b][c/2][t]

// ---------------------------------------------------------------------------
// helpers
// ---------------------------------------------------------------------------
__device__ __forceinline__ uint32_t smem_u32(const void* p) {
    uint32_t a;
    asm("{ .reg .u64 t; cvta.to.shared.u64 t, %1; cvt.u32.u64 %0, t; }" : "=r"(a) : "l"(p));
    return a;
}
__device__ __forceinline__ uint32_t bfpack(float lo, float hi) {
    uint32_t r;
    asm("cvt.rn.bf16x2.f32 %0, %1, %2;" : "=r"(r) : "f"(hi), "f"(lo));
    return r;
}
__device__ __forceinline__ uint16_t bfu(float x) {
    uint16_t r;
    asm("cvt.rn.bf16.f32 %0, %1;" : "=h"(r) : "f"(x));
    return r;
}
__device__ __forceinline__ float ubf(uint32_t bits16) {
    return __uint_as_float(bits16 << 16);
}
__device__ __forceinline__ void cp16(uint32_t dst, const void* src) {
    asm volatile("cp.async.cg.shared.global [%0], [%1], 16;" :: "r"(dst), "l"(src));
}
__device__ __forceinline__ void cp_commit() { asm volatile("cp.async.commit_group;"); }
__device__ __forceinline__ void cp_wait0() { asm volatile("cp.async.wait_group 0;" ::: "memory"); }
__device__ __forceinline__ void cp_wait1() { asm volatile("cp.async.wait_group 1;" ::: "memory"); }

// bf16 MMA m16n8k16
__device__ __forceinline__ void mma_bf16(float* c, const uint32_t* a, const uint32_t* b) {
    asm volatile(
        "mma.sync.aligned.m16n8k16.row.col.f32.bf16.bf16.f32 "
        "{%0,%1,%2,%3}, {%4,%5,%6,%7}, {%8,%9}, {%0,%1,%2,%3};"
        : "+f"(c[0]), "+f"(c[1]), "+f"(c[2]), "+f"(c[3])
        : "r"(a[0]), "r"(a[1]), "r"(a[2]), "r"(a[3]), "r"(b[0]), "r"(b[1]));
}

// ---------------------------------------------------------------------------
// Weight conversion fp32 -> bf16 (row-major, A-operand-ready)
// ---------------------------------------------------------------------------
__global__ void conv_w(const float* __restrict__ src, uint32_t* __restrict__ dst, int n4) {
    int i = blockIdx.x * 256 + threadIdx.x;
    if (i < n4) {
        float4 v = ((const float4*)src)[i];
        uint2 o;
        o.x = bfpack(v.x, v.y);
        o.y = bfpack(v.z, v.w);
        ((uint2*)dst)[i] = o;
    }
}

// ---------------------------------------------------------------------------
// GroupNorm: one block per (batch, group); writes c-pair-packed bf16.
// ---------------------------------------------------------------------------
__global__ __launch_bounds__(1024) void gn_kernel(const float* __restrict__ x,
                                                  const float* __restrict__ w,
                                                  const float* __restrict__ b,
                                                  uint32_t* __restrict__ xnp) {
    int batch = blockIdx.x >> 5;
    int g = blockIdx.x & 31;
    const float4* xp = (const float4*)(x + ((size_t)batch * 1024 + g * 32) * 1024);

    float4 va[4], vb[4];
    float s = 0.f, ss = 0.f;
#pragma unroll
    for (int r = 0; r < 4; r++) {
        int u = r * 1024 + threadIdx.x;
        int cp = u >> 8, t4 = u & 255;
        va[r] = xp[cp * 512 + t4];           // channel 2cp   (row = 2cp*256 float4s)
        vb[r] = xp[cp * 512 + 256 + t4];     // channel 2cp+1
        s += va[r].x + va[r].y + va[r].z + va[r].w + vb[r].x + vb[r].y + vb[r].z + vb[r].w;
        ss += va[r].x * va[r].x + va[r].y * va[r].y + va[r].z * va[r].z + va[r].w * va[r].w
            + vb[r].x * vb[r].x + vb[r].y * vb[r].y + vb[r].z * vb[r].z + vb[r].w * vb[r].w;
    }
#pragma unroll
    for (int o = 16; o; o >>= 1) {
        s  += __shfl_xor_sync(0xffffffffu, s, o);
        ss += __shfl_xor_sync(0xffffffffu, ss, o);
    }
    __shared__ float red[66];
    int warp = threadIdx.x >> 5, lane = threadIdx.x & 31;
    if (lane == 0) { red[warp] = s; red[warp + 32] = ss; }
    __syncthreads();
    if (threadIdx.x == 0) {
        float ts = 0.f, tss = 0.f;
#pragma unroll
        for (int i = 0; i < 32; i++) { ts += red[i]; tss += red[i + 32]; }
        float mu = ts * (1.f / 32768.f);
        float var = tss * (1.f / 32768.f) - mu * mu;
        red[64] = mu;
        red[65] = rsqrtf(var + 1e-5f);
    }
    __syncthreads();
    float mu = red[64], inv = red[65];
#pragma unroll
    for (int r = 0; r < 4; r++) {
        int u = r * 1024 + threadIdx.x;
        int cp = u >> 8, t4 = u & 255;
        int c0 = g * 32 + 2 * cp, c1 = c0 + 1;
        float s0 = inv * w[c0], h0 = b[c0] - mu * s0;
        float s1 = inv * w[c1], h1 = b[c1] - mu * s1;
        uint4 o;
        o.x = bfpack(va[r].x * s0 + h0, vb[r].x * s1 + h1);
        o.y = bfpack(va[r].y * s0 + h0, vb[r].y * s1 + h1);
        o.z = bfpack(va[r].z * s0 + h0, vb[r].z * s1 + h1);
        o.w = bfpack(va[r].w * s0 + h0, vb[r].w * s1 + h1);
        ((uint4*)(xnp + ((size_t)(batch * 512 + g * 16 + cp)) * 1024))[t4] = o;
    }
}

// ---------------------------------------------------------------------------
// bf16 tensor-core GEMM: out[z,o,t] = sum_k W[o,k]*X[z,k,t] + bias[o] (+R)
// A: bf16 [128][32] pitch 20 words. B: packed pairs [16][128] pitch 136 words.
// CTA 128x128, 256 threads (8 warps 4m x 2n), K-tile 32, double-buffered.
// BF16OUT: write bf16 pairs; else fp32 + residual.
// ---------------------------------------------------------------------------
#define APW 20
#define BPW 136
#define GEMM_SMEM ((2 * 128 * APW + 2 * 16 * BPW) * 4)

template <bool BF16OUT>
__global__ __launch_bounds__(256, 2) void gemm_bf16(const uint16_t* __restrict__ Wb,
                                                    const uint32_t* __restrict__ Xp,
                                                    const float* __restrict__ bias,
                                                    const float* __restrict__ R,
                                                    void* __restrict__ outv, int O) {
    extern __shared__ float sm[];
    uint32_t* sA = (uint32_t*)sm;                 // [2][128][APW]
    uint32_t* sB = sA + 2 * 128 * APW;            // [2][16][BPW]

    const int tid = threadIdx.x;
    const int wid = tid >> 5, lane = tid & 31;
    const int gid = lane >> 2, tg = lane & 3;
    const int warp_m = (wid & 3) * 32, warp_n = (wid >> 2) * 64;

    const int t0 = blockIdx.x * 128, o0 = blockIdx.y * 128, z = blockIdx.z;
    const uint32_t* Xb = Xp + (size_t)z * 512 * 1024;

    float c[2][8][4];
#pragma unroll
    for (int mt = 0; mt < 2; mt++)
#pragma unroll
        for (int nt = 0; nt < 8; nt++)
#pragma unroll
            for (int e = 0; e < 4; e++) c[mt][nt][e] = 0.f;

    uint32_t aA = smem_u32(sA), aB = smem_u32(sB);

    auto issue = [&](int buf, int kt) {
        const int k0 = kt * 32;          // element k base
        const int kp0 = kt * 16;         // pair-row base
        uint32_t bA = aA + (uint32_t)(buf * 128 * APW * 4);
        uint32_t bB = aB + (uint32_t)(buf * 16 * BPW * 4);
#pragma unroll
        for (int i = 0; i < 2; i++) {
            int id = tid * 2 + i;                 // 0..511
            int row = id >> 2, gr = id & 3;       // A: 128 rows x 4 granules(16B)
            cp16(bA + (uint32_t)(row * APW * 4 + gr * 16),
                 Wb + (size_t)(o0 + row) * 1024 + k0 + gr * 8);
        }
#pragma unroll
        for (int i = 0; i < 2; i++) {
            int id = tid * 2 + i;
            int row = id >> 5, gw = id & 31;      // B: 16 rows x 32 granules
            cp16(bB + (uint32_t)(row * BPW * 4 + gw * 16),
                 Xb + (size_t)(kp0 + row) * 1024 + t0 + gw * 4);
        }
        cp_commit();
    };

    issue(0, 0);

    for (int kt = 0; kt < 32; kt++) {
        const int buf = kt & 1;
        if (kt + 1 < 32) {
            issue(buf ^ 1, kt + 1);
            cp_wait1();
        } else {
            cp_wait0();
        }
        __syncthreads();

        const uint32_t* wb = sA + buf * 128 * APW;
        const uint32_t* xb = sB + buf * 16 * BPW;

#pragma unroll
        for (int ks = 0; ks < 2; ks++) {
            const int kw = ks * 8;
            uint32_t af[2][4];
#pragma unroll
            for (int mt = 0; mt < 2; mt++) {
                const uint32_t* wr = wb + (warp_m + mt * 16 + gid) * APW + kw + tg;
                af[mt][0] = wr[0];
                af[mt][1] = wr[8 * APW];
                af[mt][2] = wr[4];
                af[mt][3] = wr[8 * APW + 4];
            }
            uint32_t bf[8][2];
#pragma unroll
            for (int nt = 0; nt < 8; nt++) {
                const uint32_t* xr = xb + (kw + tg) * BPW + warp_n + nt * 8 + gid;
                bf[nt][0] = xr[0];
                bf[nt][1] = xr[4 * BPW];
            }
#pragma unroll
            for (int mt = 0; mt < 2; mt++)
#pragma unroll
                for (int nt = 0; nt < 8; nt++)
                    mma_bf16(c[mt][nt], af[mt], bf[nt]);
        }
        __syncthreads();
    }

#pragma unroll
    for (int mt = 0; mt < 2; mt++) {
#pragma unroll
        for (int half = 0; half < 2; half++) {
            int o = o0 + warp_m + mt * 16 + gid + half * 8;
            float bv = bias[o];
            size_t rowbase = ((size_t)z * O + o) * 1024;
#pragma unroll
            for (int nt = 0; nt < 8; nt++) {
                int t = t0 + warp_n + nt * 8 + tg * 2;
                float vx = c[mt][nt][half * 2 + 0] + bv;
                float vy = c[mt][nt][half * 2 + 1] + bv;
                if (BF16OUT) {
                    ((uint32_t*)outv)[(rowbase + t) >> 1] = bfpack(vx, vy);
                } else {
                    float2 rr = *(const float2*)(R + rowbase + t);
                    float2 v = { vx + rr.x, vy + rr.y };
                    *(float2*)((float*)outv + rowbase + t) = v;
                }
            }
        }
    }
}

// ---------------------------------------------------------------------------
// Flash attention, bf16 mma, warp-owns-columns.
// Block = (b,h) x 64-query tile; 256 threads = 8 warps, warp owns 8 cols.
// All smem operands pitch 36 words (banks 4*gid+tg, conflict-free).
//   Qt[i][c] bf16 (B op), Kt[j][c] bf16 (A op), Vs[c][j] bf16 (A op),
//   St[i][j] bf16 (B op, P transposed; packed via shfl).
// ---------------------------------------------------------------------------
#define TPW 36
#define ATTN_SMEM (4 * 64 * TPW * 4)

__global__ __launch_bounds__(256, 2) void attn_mma(const uint16_t* __restrict__ qkvb,
                                                   uint32_t* __restrict__ attnp) {
    extern __shared__ float smf[];
    uint32_t* Qt = (uint32_t*)smf;          // [64 i][TPW]
    uint32_t* Kt = Qt + 64 * TPW;           // [64 j][TPW]
    uint32_t* Vs = Kt + 64 * TPW;           // [64 c][TPW]
    uint32_t* St = Vs + 64 * TPW;           // [64 i][TPW]

    const int bh = blockIdx.y;
    const int b = bh >> 4, h = bh & 15;
    const int t0 = blockIdx.x * 64;
    const uint16_t* qg = qkvb + ((size_t)b * 3072 + h * 192) * 1024;
    const uint16_t* kg = qg + 64 * 1024;
    const uint32_t* vg = (const uint32_t*)(qg + 128 * 1024);

    const int tid = threadIdx.x, wid = tid >> 5, lane = tid & 31;
    const int gid = lane >> 2, tg = lane & 3;
    const int i0 = wid * 8;

    // Q tile: Qt[i][cpair] = {Q[2cp][t0+i], Q[2cp+1][t0+i]}
#pragma unroll
    for (int r = 0; r < 8; r++) {
        int u = r * 256 + tid;
        int i = u & 63, cp = u >> 6;
        uint32_t lo = qg[(size_t)(2 * cp) * 1024 + t0 + i];
        uint32_t hi = qg[(size_t)(2 * cp + 1) * 1024 + t0 + i];
        Qt[i * TPW + cp] = lo | (hi << 16);
    }

    float o[4][4];
#pragma unroll
    for (int mt = 0; mt < 4; mt++)
#pragma unroll
        for (int e = 0; e < 4; e++) o[mt][e] = 0.f;
    float m_run[2] = { -1e30f, -1e30f };
    float l_run[2] = { 0.f, 0.f };

    for (int s0 = 0; s0 < 1024; s0 += 64) {
        __syncthreads();

        // K transposed+packed: Kt[j][cp]
#pragma unroll
        for (int r = 0; r < 8; r++) {
            int u = r * 256 + tid;
            int j = u & 63, cp = u >> 6;
            uint32_t lo = kg[(size_t)(2 * cp) * 1024 + s0 + j];
            uint32_t hi = kg[(size_t)(2 * cp + 1) * 1024 + s0 + j];
            Kt[j * TPW + cp] = lo | (hi << 16);
        }
        // V natural: Vs[c][jw] (j pairs contiguous in gmem)
#pragma unroll
        for (int r = 0; r < 8; r++) {
            int u = r * 256 + tid;
            int cc = u >> 5, jw = u & 31;
            Vs[cc * TPW + jw] = vg[((size_t)cc * 1024 + s0) / 2 + jw];
        }
        __syncthreads();

        // ---- S = Kt * Q : all 64 j for this warp's 8 cols ----
        float sc[4][4];
#pragma unroll
        for (int mt = 0; mt < 4; mt++)
#pragma unroll
            for (int e = 0; e < 4; e++) sc[mt][e] = 0.f;

#pragma unroll
        for (int ks = 0; ks < 4; ks++) {
            int kw = ks * 8;
            uint32_t bb[2];
            bb[0] = Qt[(i0 + gid) * TPW + kw + tg];
            bb[1] = Qt[(i0 + gid) * TPW + kw + tg + 4];
#pragma unroll
            for (int mt = 0; mt < 4; mt++) {
                uint32_t a[4];
                a[0] = Kt[(mt * 16 + gid) * TPW + kw + tg];
                a[1] = Kt[(mt * 16 + gid + 8) * TPW + kw + tg];
                a[2] = Kt[(mt * 16 + gid) * TPW + kw + tg + 4];
                a[3] = Kt[(mt * 16 + gid + 8) * TPW + kw + tg + 4];
                mma_bf16(sc[mt], a, bb);
            }
        }

        // ---- warp-local online softmax (cols i0+2tg, i0+2tg+1) ----
        float alpha[2], psum[2];
#pragma unroll
        for (int e = 0; e < 2; e++) {
            float cm = fmaxf(fmaxf(sc[0][e], sc[0][e + 2]), fmaxf(sc[1][e], sc[1][e + 2]));
            cm = fmaxf(cm, fmaxf(fmaxf(sc[2][e], sc[2][e + 2]), fmaxf(sc[3][e], sc[3][e + 2])));
            cm *= 0.125f;
#pragma unroll
            for (int mk = 4; mk <= 16; mk <<= 1)
                cm = fmaxf(cm, __shfl_xor_sync(0xffffffffu, cm, mk));
            float mn = fmaxf(m_run[e], cm);
            alpha[e] = __expf(m_run[e] - mn);
            m_run[e] = mn;
            psum[e] = 0.f;
        }
        // P -> St (bf16, packed over j via shfl with gid^1 partner)
#pragma unroll
        for (int mt = 0; mt < 4; mt++) {
#pragma unroll
            for (int e = 0; e < 2; e++) {
                uint32_t h0 = bfu(__expf(sc[mt][e] * 0.125f - m_run[e]));
                uint32_t h1 = bfu(__expf(sc[mt][e + 2] * 0.125f - m_run[e]));
                psum[e] += ubf(h0) + ubf(h1);
                uint32_t w = h0 | (h1 << 16);
                uint32_t pw = __shfl_xor_sync(0xffffffffu, w, 4);
                if ((gid & 1) == 0) {
                    int i = i0 + 2 * tg + e;
                    St[i * TPW + (mt * 16 + gid) / 2] = (w & 0xffffu) | (pw << 16);
                    St[i * TPW + (mt * 16 + gid + 8) / 2] = (w >> 16) | (pw & 0xffff0000u);
                }
            }
        }
#pragma unroll
        for (int e = 0; e < 2; e++) {
#pragma unroll
            for (int mk = 4; mk <= 16; mk <<= 1)
                psum[e] += __shfl_xor_sync(0xffffffffu, psum[e], mk);
            l_run[e] = l_run[e] * alpha[e] + psum[e];
        }
#pragma unroll
        for (int mt = 0; mt < 4; mt++) {
            o[mt][0] *= alpha[0]; o[mt][2] *= alpha[0];
            o[mt][1] *= alpha[1]; o[mt][3] *= alpha[1];
        }
        __syncwarp();

        // ---- O += V * P ----
#pragma unroll
        for (int ks = 0; ks < 4; ks++) {
            int kw = ks * 8;
            uint32_t bb[2];
            bb[0] = St[(i0 + gid) * TPW + kw + tg];
            bb[1] = St[(i0 + gid) * TPW + kw + tg + 4];
#pragma unroll
            for (int mt = 0; mt < 4; mt++) {
                uint32_t a[4];
                a[0] = Vs[(mt * 16 + gid) * TPW + kw + tg];
                a[1] = Vs[(mt * 16 + gid + 8) * TPW + kw + tg];
                a[2] = Vs[(mt * 16 + gid) * TPW + kw + tg + 4];
                a[3] = Vs[(mt * 16 + gid + 8) * TPW + kw + tg + 4];
                mma_bf16(o[mt], a, bb);
            }
        }
    }

    // normalize + write packed bf16 pairs over c (shfl gid^1 partner)
    float li0 = 1.f / l_run[0], li1 = 1.f / l_run[1];
#pragma unroll
    for (int mt = 0; mt < 4; mt++) {
#pragma unroll
        for (int e = 0; e < 2; e++) {
            float li = e ? li1 : li0;
            uint32_t b0 = bfu(o[mt][e] * li);        // row mt*16+gid
            uint32_t b1 = bfu(o[mt][e + 2] * li);    // row mt*16+gid+8
            uint32_t w = b0 | (b1 << 16);
            uint32_t pw = __shfl_xor_sync(0xffffffffu, w, 4);
            if ((gid & 1) == 0) {
                int i = t0 + i0 + 2 * tg + e;
                int c = h * 64 + mt * 16 + gid;
                attnp[((size_t)b * 512 + c / 2) * 1024 + i] = (w & 0xffffu) | (pw << 16);
                attnp[((size_t)b * 512 + (c + 8) / 2) * 1024 + i] = (w >> 16) | (pw & 0xffff0000u);
            }
        }
    }
}

// ---------------------------------------------------------------------------
extern "C" void kernel_launch(void* const* d_in, const int* in_sizes, int n_in,
                              void* d_out, int out_size) {
    const float* x      = (const float*)d_in[0];
    const float* nw     = (const float*)d_in[1];
    const float* nb     = (const float*)d_in[2];
    const float* qkv_w  = (const float*)d_in[3];
    const float* qkv_b  = (const float*)d_in[4];
    const float* proj_w = (const float*)d_in[5];
    const float* proj_b = (const float*)d_in[6];
    float* out = (float*)d_out;

    uint16_t *wq, *wp, *qkvb;
    uint32_t *xnp, *attnp;
    cudaGetSymbolAddress((void**)&wq,    g_wq);
    cudaGetSymbolAddress((void**)&wp,    g_wp);
    cudaGetSymbolAddress((void**)&xnp,   g_xnp);
    cudaGetSymbolAddress((void**)&qkvb,  g_qkvb);
    cudaGetSymbolAddress((void**)&attnp, g_attnp);

    // 0. Weight conversion to bf16
    conv_w<<<3072, 256>>>(qkv_w, (uint32_t*)wq, 3072 * 1024 / 4);
    conv_w<<<1024, 256>>>(proj_w, (uint32_t*)wp, 1024 * 1024 / 4);

    // 1. GroupNorm -> packed bf16
    gn_kernel<<<128, 1024>>>(x, nw, nb, xnp);

    // 2. QKV projection (bf16 mma) -> bf16
    cudaFuncSetAttribute(gemm_bf16<true>, cudaFuncAttributeMaxDynamicSharedMemorySize, GEMM_SMEM);
    gemm_bf16<true><<<dim3(8, 24, 4), 256, GEMM_SMEM>>>(wq, xnp, qkv_b, nullptr, qkvb, 3072);

    // 3. Attention (bf16 mma flash) -> packed bf16
    cudaFuncSetAttribute(attn_mma, cudaFuncAttributeMaxDynamicSharedMemorySize, ATTN_SMEM);
    attn_mma<<<dim3(16, 64), 256, ATTN_SMEM>>>(qkvb, attnp);

    // 4. Output projection + bias + residual (fp32 out)
    cudaFuncSetAttribute(gemm_bf16<false>, cudaFuncAttributeMaxDynamicSharedMemorySize, GEMM_SMEM);
    gemm_bf16<false><<<dim3(8, 8, 4), 256, GEMM_SMEM>>>(wp, attnp, proj_b, x, out, 1024);
}